// round 1
// baseline (speedup 1.0000x reference)
#include <cuda_runtime.h>
#include <math.h>

#define NV    500000
#define ND    128
#define NEDGE 1000000
#define NH    8
#define NC    16

// ---------------- scratch (device globals; allocation-free launch) ----------
__device__ float  g_proj[NV];
__device__ float  g_deg[NV];          // deg, then overwritten with dinv
__device__ float4 g_m0[NV * 2];       // 8 floats per node
__device__ float4 g_m1[NV * 2];
__device__ float4 g_acc0[NV * 2];
__device__ float4 g_acc1[NV * 2];
__device__ int2   g_edge[NEDGE];      // (Se, Ie)
__device__ float  g_w[NEDGE];         // per-hyperedge normalized weight
__device__ int    g_is64;

// ---------------- dtype detection for E (int64 vs silently-downcast int32) --
__global__ void k_detect(const unsigned* __restrict__ E) {
    unsigned o = 0;
#pragma unroll
    for (int i = 0; i < 128; i++) o |= E[2 * i + 1];
    g_is64 = (o == 0) ? 1 : 0;
}

// ---------------- K1: fused proj = X@rv and A = X@W1, deg init -------------
// warp per node row; coalesced float4 loads of X.
__global__ void k_proj_w1(const float* __restrict__ X,
                          const float* __restrict__ rv,
                          const float* __restrict__ W1) {
    __shared__ float4 sW[8 * 32];   // sW[h*32 + lane] = W1 rows 4lane..4lane+3, col h
    __shared__ float4 sr[32];
    int t = threadIdx.x;
    for (int i = t; i < 1024; i += blockDim.x) {
        int d = i >> 3, h = i & 7;
        ((float*)sW)[h * 128 + d] = W1[i];
    }
    for (int i = t; i < 128; i += blockDim.x) ((float*)sr)[i] = rv[i];
    __syncthreads();

    int gw   = (blockIdx.x * blockDim.x + t) >> 5;
    int lane = t & 31;
    if (gw >= NV) return;

    float4 x = ((const float4*)X)[gw * 32 + lane];
    float4 r = sr[lane];
    float p = x.x * r.x + x.y * r.y + x.z * r.z + x.w * r.w;
    float a[8];
#pragma unroll
    for (int h = 0; h < 8; h++) {
        float4 w = sW[h * 32 + lane];
        a[h] = x.x * w.x + x.y * w.y + x.z * w.z + x.w * w.w;
    }
#pragma unroll
    for (int o = 16; o; o >>= 1) {
        p += __shfl_xor_sync(0xffffffffu, p, o);
#pragma unroll
        for (int h = 0; h < 8; h++) a[h] += __shfl_xor_sync(0xffffffffu, a[h], o);
    }
    if (lane == 0) {
        g_proj[gw] = p;
        g_m0[gw * 2]     = make_float4(a[0], a[1], a[2], a[3]);
        g_m0[gw * 2 + 1] = make_float4(a[4], a[5], a[6], a[7]);
        g_deg[gw] = 1.0f;   // identity contribution
    }
}

// ---------------- K2: per-hyperedge argmax/argmin + degree atomics ----------
__global__ void k_edges(const void* __restrict__ E) {
    int e = blockIdx.x * blockDim.x + threadIdx.x;
    if (e >= NEDGE) return;
    int idx[8];
    if (g_is64) {
        const longlong4* p = (const longlong4*)E;
        longlong4 u = p[e * 2], v = p[e * 2 + 1];
        idx[0] = (int)u.x; idx[1] = (int)u.y; idx[2] = (int)u.z; idx[3] = (int)u.w;
        idx[4] = (int)v.x; idx[5] = (int)v.y; idx[6] = (int)v.z; idx[7] = (int)v.w;
    } else {
        const int4* p = (const int4*)E;
        int4 u = p[e * 2], v = p[e * 2 + 1];
        idx[0] = u.x; idx[1] = u.y; idx[2] = u.z; idx[3] = u.w;
        idx[4] = v.x; idx[5] = v.y; idx[6] = v.z; idx[7] = v.w;
    }
    float pv[8];
#pragma unroll
    for (int k = 0; k < 8; k++) pv[k] = __ldg(&g_proj[idx[k]]);
    // strict compares -> first occurrence, matching jnp.argmax/argmin
    int S = idx[0], I = idx[0];
    float mx = pv[0], mn = pv[0];
#pragma unroll
    for (int k = 1; k < 8; k++) {
        if (pv[k] > mx) { mx = pv[k]; S = idx[k]; }
        if (pv[k] < mn) { mn = pv[k]; I = idx[k]; }
    }
    g_edge[e] = make_int2(S, I);
    atomicAdd(&g_deg[S], 0.125f);
    atomicAdd(&g_deg[I], 0.125f);
}

// ---------------- K3: dinv = rsqrt(deg); acc0 = dinv^2 * A ------------------
__global__ void k_norm() {
    int v = blockIdx.x * blockDim.x + threadIdx.x;
    if (v >= NV) return;
    float d = rsqrtf(g_deg[v]);
    g_deg[v] = d;                 // now holds dinv
    float dd = d * d;
    float4 a = g_m0[2 * v], b = g_m0[2 * v + 1];
    g_acc0[2 * v]     = make_float4(dd * a.x, dd * a.y, dd * a.z, dd * a.w);
    g_acc0[2 * v + 1] = make_float4(dd * b.x, dd * b.y, dd * b.z, dd * b.w);
}

// ---------------- scatter: acc[Se] += w*M[Ie]; acc[Ie] += w*M[Se] -----------
__device__ __forceinline__ void red4(float4* p, float w, float4 v) {
    atomicAdd(p, make_float4(w * v.x, w * v.y, w * v.z, w * v.w));
}

__global__ void k_scatter(int msel, int asel, int first) {
    int e = blockIdx.x * blockDim.x + threadIdx.x;
    if (e >= NEDGE) return;
    int2 si = g_edge[e];
    float w;
    if (first) {
        w = 0.125f * __ldg(&g_deg[si.x]) * __ldg(&g_deg[si.y]);
        g_w[e] = w;
    } else {
        w = g_w[e];
    }
    const float4* M = msel ? g_m1 : g_m0;
    float4* A = asel ? g_acc1 : g_acc0;
    float4 a0 = __ldg(&M[2 * si.y]), a1 = __ldg(&M[2 * si.y + 1]);
    float4 b0 = __ldg(&M[2 * si.x]), b1 = __ldg(&M[2 * si.x + 1]);
    red4(&A[2 * si.x],     w, a0);
    red4(&A[2 * si.x + 1], w, a1);
    red4(&A[2 * si.y],     w, b0);
    red4(&A[2 * si.y + 1], w, b1);
}

// ---------------- K5: H1 = relu(acc0+b1); m1 = H1@W2; acc1 = dinv^2*m1 ------
__global__ void k_layer2(const float* __restrict__ W2, const float* __restrict__ b1) {
    __shared__ float sW[64], sb[8];
    int t = threadIdx.x;
    if (t < 64) sW[t] = W2[t];
    if (t < 8)  sb[t] = b1[t];
    __syncthreads();
    int v = blockIdx.x * blockDim.x + t;
    if (v >= NV) return;
    float4 a = g_acc0[2 * v], b = g_acc0[2 * v + 1];
    float h[8];
    h[0] = fmaxf(a.x + sb[0], 0.f); h[1] = fmaxf(a.y + sb[1], 0.f);
    h[2] = fmaxf(a.z + sb[2], 0.f); h[3] = fmaxf(a.w + sb[3], 0.f);
    h[4] = fmaxf(b.x + sb[4], 0.f); h[5] = fmaxf(b.y + sb[5], 0.f);
    h[6] = fmaxf(b.z + sb[6], 0.f); h[7] = fmaxf(b.w + sb[7], 0.f);
    float m[8];
#pragma unroll
    for (int j = 0; j < 8; j++) {
        float s = 0.f;
#pragma unroll
        for (int k = 0; k < 8; k++) s += h[k] * sW[k * 8 + j];
        m[j] = s;
    }
    float d = g_deg[v]; float dd = d * d;
    g_m1[2 * v]       = make_float4(m[0], m[1], m[2], m[3]);
    g_m1[2 * v + 1]   = make_float4(m[4], m[5], m[6], m[7]);
    g_acc1[2 * v]     = make_float4(dd * m[0], dd * m[1], dd * m[2], dd * m[3]);
    g_acc1[2 * v + 1] = make_float4(dd * m[4], dd * m[5], dd * m[6], dd * m[7]);
}

// ---------------- K7: H2 = relu(acc1+b2); m0 = H2; acc0 = dinv^2*H2 ---------
// (uses spmm(H@W3) = spmm(H)@W3 so the last scatter runs at F=8, not 16)
__global__ void k_layer3pre(const float* __restrict__ b2) {
    __shared__ float sb[8];
    int t = threadIdx.x;
    if (t < 8) sb[t] = b2[t];
    __syncthreads();
    int v = blockIdx.x * blockDim.x + t;
    if (v >= NV) return;
    float4 a = g_acc1[2 * v], b = g_acc1[2 * v + 1];
    float4 h0 = make_float4(fmaxf(a.x + sb[0], 0.f), fmaxf(a.y + sb[1], 0.f),
                            fmaxf(a.z + sb[2], 0.f), fmaxf(a.w + sb[3], 0.f));
    float4 h1 = make_float4(fmaxf(b.x + sb[4], 0.f), fmaxf(b.y + sb[5], 0.f),
                            fmaxf(b.z + sb[6], 0.f), fmaxf(b.w + sb[7], 0.f));
    float d = g_deg[v]; float dd = d * d;
    g_m0[2 * v]       = h0;
    g_m0[2 * v + 1]   = h1;
    g_acc0[2 * v]     = make_float4(dd * h0.x, dd * h0.y, dd * h0.z, dd * h0.w);
    g_acc0[2 * v + 1] = make_float4(dd * h1.x, dd * h1.y, dd * h1.z, dd * h1.w);
}

// ---------------- K9: out = sigmoid( relu(acc0@W3 + b3) @ fc_w + fc_b ) -----
__global__ void k_out(const float* __restrict__ W3, const float* __restrict__ b3,
                      const float* __restrict__ fcw, const float* __restrict__ fcb,
                      float* __restrict__ out) {
    __shared__ float sW[8 * 16], sb3[16], sfw[16], sfb;
    int t = threadIdx.x;
    if (t < 128) sW[t] = W3[t];
    if (t < 16) { sb3[t] = b3[t]; sfw[t] = fcw[t]; }
    if (t == 0) sfb = fcb[0];
    __syncthreads();
    int v = blockIdx.x * blockDim.x + t;
    if (v >= NV) return;
    float4 a = g_acc0[2 * v], b = g_acc0[2 * v + 1];
    float s[8] = {a.x, a.y, a.z, a.w, b.x, b.y, b.z, b.w};
    float logit = sfb;
#pragma unroll
    for (int c = 0; c < 16; c++) {
        float tt = sb3[c];
#pragma unroll
        for (int h = 0; h < 8; h++) tt += s[h] * sW[h * 16 + c];
        logit += fmaxf(tt, 0.f) * sfw[c];
    }
    out[v] = 1.0f / (1.0f + expf(-logit));
}

// ---------------- launch ----------------------------------------------------
extern "C" void kernel_launch(void* const* d_in, const int* in_sizes, int n_in,
                              void* d_out, int out_size) {
    const float* X   = (const float*)d_in[0];
    const void*  E   = d_in[1];
    const float* rv  = (const float*)d_in[2];
    const float* W1  = (const float*)d_in[3];
    const float* b1  = (const float*)d_in[4];
    const float* W2  = (const float*)d_in[5];
    const float* b2  = (const float*)d_in[6];
    const float* W3  = (const float*)d_in[7];
    const float* b3  = (const float*)d_in[8];
    const float* fcw = (const float*)d_in[9];
    const float* fcb = (const float*)d_in[10];
    float* out = (float*)d_out;

    const int NB_V = (NV + 255) / 256;                 // 1954
    const int NB_E = (NEDGE + 255) / 256;              // 3907
    const int NB_W = (NV * 32 + 255) / 256;            // 62500 (warp per node)

    k_detect<<<1, 1>>>((const unsigned*)E);
    k_proj_w1<<<NB_W, 256>>>(X, rv, W1);
    k_edges<<<NB_E, 256>>>(E);
    k_norm<<<NB_V, 256>>>();
    k_scatter<<<NB_E, 256>>>(0, 0, 1);                 // layer 1: M=m0 -> acc0
    k_layer2<<<NB_V, 256>>>(W2, b1);
    k_scatter<<<NB_E, 256>>>(1, 1, 0);                 // layer 2: M=m1 -> acc1
    k_layer3pre<<<NB_V, 256>>>(b2);
    k_scatter<<<NB_E, 256>>>(0, 0, 0);                 // layer 3: M=m0 -> acc0 (F=8)
    k_out<<<NB_V, 256>>>(W3, b3, fcw, fcb, out);
}

// round 3
// speedup vs baseline: 1.4566x; 1.4566x over previous
#include <cuda_runtime.h>
#include <math.h>

#define NV    500000
#define ND    128
#define NEDGE 1000000

// ---------------- scratch (device globals; allocation-free launch) ----------
__device__ float  g_proj[NV];
__device__ float  g_deg[NV];          // deg, then overwritten with dinv
__device__ float4 g_m0[NV * 2];       // 8 floats per node
__device__ float4 g_m1[NV * 2];
__device__ float4 g_acc0[NV * 2];
__device__ float4 g_acc1[NV * 2];
__device__ int2   g_edge[NEDGE];      // (Se, Ie)
__device__ float  g_w[NEDGE];         // per-hyperedge normalized weight
__device__ int    g_is64;

// ---------------- K1: fused proj = X@rv and A = X@W1, deg init -------------
// 8 lanes per row, 4 rows per warp: MLP=4 per lane, 3-round reductions.
__global__ void __launch_bounds__(256) k_proj_w1(
        const float* __restrict__ X,
        const float* __restrict__ rv,
        const float* __restrict__ W1,
        const unsigned* __restrict__ E) {
    // dtype detection prelude (E int64 vs silently-downcast int32):
    // values < 500000 => int64 high words are all zero.
    if (blockIdx.x == 0 && threadIdx.x == 0) {
        unsigned o = 0;
#pragma unroll
        for (int i = 0; i < 128; i++) o |= E[2 * i + 1];
        g_is64 = (o == 0) ? 1 : 0;
    }

    __shared__ float4 sW[8 * 32];   // sW[h*32 + d4] = W1 rows 4*d4..4*d4+3, col h
    __shared__ float4 sr[32];
    int t = threadIdx.x;
    for (int i = t; i < 1024; i += 256) {
        int d = i >> 3, h = i & 7;
        ((float*)sW)[h * 128 + d] = W1[i];
    }
    if (t < 128) ((float*)sr)[t] = rv[t];
    __syncthreads();

    int lane = t & 31;
    int sub  = lane & 7;            // 0..7 : position within row
    int rloc = lane >> 3;           // 0..3 : row within warp
    int warp = (blockIdx.x * 256 + t) >> 5;
    int row  = warp * 4 + rloc;
    if (row >= NV) return;

    const float4* Xr = (const float4*)X + (size_t)row * 32;
    float p = 0.f;
    float a[8] = {0.f, 0.f, 0.f, 0.f, 0.f, 0.f, 0.f, 0.f};
#pragma unroll
    for (int i = 0; i < 4; i++) {
        int d4 = sub + i * 8;
        float4 x = __ldcs(&Xr[d4]);
        float4 r = sr[d4];
        p += x.x * r.x + x.y * r.y + x.z * r.z + x.w * r.w;
#pragma unroll
        for (int h = 0; h < 8; h++) {
            float4 w = sW[h * 32 + d4];
            a[h] += x.x * w.x + x.y * w.y + x.z * w.z + x.w * w.w;
        }
    }
    // reduce across the 8 lanes of this row
#pragma unroll
    for (int o = 4; o; o >>= 1) {
        p += __shfl_down_sync(0xffffffffu, p, o);
#pragma unroll
        for (int h = 0; h < 8; h++) a[h] += __shfl_down_sync(0xffffffffu, a[h], o);
    }
    if (sub == 0) {
        g_proj[row] = p;
        g_m0[row * 2]     = make_float4(a[0], a[1], a[2], a[3]);
        g_m0[row * 2 + 1] = make_float4(a[4], a[5], a[6], a[7]);
        g_deg[row] = 1.0f;   // identity contribution
    }
}

// ---------------- K2: per-hyperedge argmax/argmin + degree atomics ----------
__global__ void __launch_bounds__(256) k_edges(const void* __restrict__ E) {
    int e = blockIdx.x * blockDim.x + threadIdx.x;
    if (e >= NEDGE) return;
    int idx[8];
    if (g_is64) {
        const longlong4* p = (const longlong4*)E;
        longlong4 u = p[e * 2], v = p[e * 2 + 1];
        idx[0] = (int)u.x; idx[1] = (int)u.y; idx[2] = (int)u.z; idx[3] = (int)u.w;
        idx[4] = (int)v.x; idx[5] = (int)v.y; idx[6] = (int)v.z; idx[7] = (int)v.w;
    } else {
        const int4* p = (const int4*)E;
        int4 u = p[e * 2], v = p[e * 2 + 1];
        idx[0] = u.x; idx[1] = u.y; idx[2] = u.z; idx[3] = u.w;
        idx[4] = v.x; idx[5] = v.y; idx[6] = v.z; idx[7] = v.w;
    }
    float pv[8];
#pragma unroll
    for (int k = 0; k < 8; k++) pv[k] = __ldg(&g_proj[idx[k]]);
    // strict compares -> first occurrence, matching jnp.argmax/argmin
    int S = idx[0], I = idx[0];
    float mx = pv[0], mn = pv[0];
#pragma unroll
    for (int k = 1; k < 8; k++) {
        if (pv[k] > mx) { mx = pv[k]; S = idx[k]; }
        if (pv[k] < mn) { mn = pv[k]; I = idx[k]; }
    }
    g_edge[e] = make_int2(S, I);
    atomicAdd(&g_deg[S], 0.125f);
    atomicAdd(&g_deg[I], 0.125f);
}

// ---------------- K3: dinv = rsqrt(deg); acc0 = dinv^2 * A ------------------
__global__ void __launch_bounds__(256) k_norm() {
    int v = blockIdx.x * blockDim.x + threadIdx.x;
    if (v >= NV) return;
    float d = rsqrtf(g_deg[v]);
    g_deg[v] = d;                 // now holds dinv
    float dd = d * d;
    float4 a = g_m0[2 * v], b = g_m0[2 * v + 1];
    g_acc0[2 * v]     = make_float4(dd * a.x, dd * a.y, dd * a.z, dd * a.w);
    g_acc0[2 * v + 1] = make_float4(dd * b.x, dd * b.y, dd * b.z, dd * b.w);
}

// ---------------- scatter: acc[dst] += w*M[src], 2 threads per edge ---------
__device__ __forceinline__ void red4(float4* p, float w, float4 v) {
    atomicAdd(p, make_float4(w * v.x, w * v.y, w * v.z, w * v.w));
}

__global__ void __launch_bounds__(256) k_scatter(int msel, int asel, int first) {
    int t = blockIdx.x * blockDim.x + threadIdx.x;
    int e = t >> 1, side = t & 1;
    if (e >= NEDGE) return;
    int2 si = g_edge[e];
    float w;
    if (first) {
        w = 0.125f * __ldg(&g_deg[si.x]) * __ldg(&g_deg[si.y]);
        if (side == 0) g_w[e] = w;
    } else {
        w = g_w[e];
    }
    int dst = side ? si.y : si.x;
    int src = side ? si.x : si.y;
    const float4* M = msel ? g_m1 : g_m0;
    float4* A = asel ? g_acc1 : g_acc0;
    float4 a0 = __ldg(&M[2 * src]), a1 = __ldg(&M[2 * src + 1]);
    red4(&A[2 * dst],     w, a0);
    red4(&A[2 * dst + 1], w, a1);
}

// ---------------- K5: H1 = relu(acc0+b1); m1 = H1@W2; acc1 = dinv^2*m1 ------
__global__ void __launch_bounds__(256) k_layer2(const float* __restrict__ W2,
                                                const float* __restrict__ b1) {
    __shared__ float sW[64], sb[8];
    int t = threadIdx.x;
    if (t < 64) sW[t] = W2[t];
    if (t < 8)  sb[t] = b1[t];
    __syncthreads();
    int v = blockIdx.x * blockDim.x + t;
    if (v >= NV) return;
    float4 a = g_acc0[2 * v], b = g_acc0[2 * v + 1];
    float h[8];
    h[0] = fmaxf(a.x + sb[0], 0.f); h[1] = fmaxf(a.y + sb[1], 0.f);
    h[2] = fmaxf(a.z + sb[2], 0.f); h[3] = fmaxf(a.w + sb[3], 0.f);
    h[4] = fmaxf(b.x + sb[4], 0.f); h[5] = fmaxf(b.y + sb[5], 0.f);
    h[6] = fmaxf(b.z + sb[6], 0.f); h[7] = fmaxf(b.w + sb[7], 0.f);
    float m[8];
#pragma unroll
    for (int j = 0; j < 8; j++) {
        float s = 0.f;
#pragma unroll
        for (int k = 0; k < 8; k++) s += h[k] * sW[k * 8 + j];
        m[j] = s;
    }
    float d = g_deg[v]; float dd = d * d;
    g_m1[2 * v]       = make_float4(m[0], m[1], m[2], m[3]);
    g_m1[2 * v + 1]   = make_float4(m[4], m[5], m[6], m[7]);
    g_acc1[2 * v]     = make_float4(dd * m[0], dd * m[1], dd * m[2], dd * m[3]);
    g_acc1[2 * v + 1] = make_float4(dd * m[4], dd * m[5], dd * m[6], dd * m[7]);
}

// ---------------- K7: H2 = relu(acc1+b2); m0 = H2; acc0 = dinv^2*H2 ---------
// (uses spmm(H@W3) = spmm(H)@W3 so the last scatter runs at F=8, not 16)
__global__ void __launch_bounds__(256) k_layer3pre(const float* __restrict__ b2) {
    __shared__ float sb[8];
    int t = threadIdx.x;
    if (t < 8) sb[t] = b2[t];
    __syncthreads();
    int v = blockIdx.x * blockDim.x + t;
    if (v >= NV) return;
    float4 a = g_acc1[2 * v], b = g_acc1[2 * v + 1];
    float4 h0 = make_float4(fmaxf(a.x + sb[0], 0.f), fmaxf(a.y + sb[1], 0.f),
                            fmaxf(a.z + sb[2], 0.f), fmaxf(a.w + sb[3], 0.f));
    float4 h1 = make_float4(fmaxf(b.x + sb[4], 0.f), fmaxf(b.y + sb[5], 0.f),
                            fmaxf(b.z + sb[6], 0.f), fmaxf(b.w + sb[7], 0.f));
    float d = g_deg[v]; float dd = d * d;
    g_m0[2 * v]       = h0;
    g_m0[2 * v + 1]   = h1;
    g_acc0[2 * v]     = make_float4(dd * h0.x, dd * h0.y, dd * h0.z, dd * h0.w);
    g_acc0[2 * v + 1] = make_float4(dd * h1.x, dd * h1.y, dd * h1.z, dd * h1.w);
}

// ---------------- K9: out = sigmoid( relu(acc0@W3 + b3) @ fc_w + fc_b ) -----
__global__ void __launch_bounds__(256) k_out(
        const float* __restrict__ W3, const float* __restrict__ b3,
        const float* __restrict__ fcw, const float* __restrict__ fcb,
        float* __restrict__ out) {
    __shared__ float sW[8 * 16], sb3[16], sfw[16], sfb;
    int t = threadIdx.x;
    if (t < 128) sW[t] = W3[t];
    if (t < 16) { sb3[t] = b3[t]; sfw[t] = fcw[t]; }
    if (t == 0) sfb = fcb[0];
    __syncthreads();
    int v = blockIdx.x * blockDim.x + t;
    if (v >= NV) return;
    float4 a = g_acc0[2 * v], b = g_acc0[2 * v + 1];
    float s[8] = {a.x, a.y, a.z, a.w, b.x, b.y, b.z, b.w};
    float logit = sfb;
#pragma unroll
    for (int c = 0; c < 16; c++) {
        float tt = sb3[c];
#pragma unroll
        for (int h = 0; h < 8; h++) tt += s[h] * sW[h * 16 + c];
        logit += fmaxf(tt, 0.f) * sfw[c];
    }
    out[v] = 1.0f / (1.0f + expf(-logit));
}

// ---------------- launch ----------------------------------------------------
extern "C" void kernel_launch(void* const* d_in, const int* in_sizes, int n_in,
                              void* d_out, int out_size) {
    const float* X   = (const float*)d_in[0];
    const void*  E   = d_in[1];
    const float* rv  = (const float*)d_in[2];
    const float* W1  = (const float*)d_in[3];
    const float* b1  = (const float*)d_in[4];
    const float* W2  = (const float*)d_in[5];
    const float* b2  = (const float*)d_in[6];
    const float* W3  = (const float*)d_in[7];
    const float* b3  = (const float*)d_in[8];
    const float* fcw = (const float*)d_in[9];
    const float* fcb = (const float*)d_in[10];
    float* out = (float*)d_out;

    const int NB_V = (NV + 255) / 256;                 // 1954
    const int NB_E = (NEDGE + 255) / 256;              // 3907
    const int NB_E2 = (2 * NEDGE + 255) / 256;         // 7813 (2 threads/edge)
    const int NB_W = (NV * 8 + 255) / 256;             // 15625 (8 lanes per row)

    k_proj_w1<<<NB_W, 256>>>(X, rv, W1, (const unsigned*)E);
    k_edges<<<NB_E, 256>>>(E);
    k_norm<<<NB_V, 256>>>();
    k_scatter<<<NB_E2, 256>>>(0, 0, 1);                // layer 1: M=m0 -> acc0
    k_layer2<<<NB_V, 256>>>(W2, b1);
    k_scatter<<<NB_E2, 256>>>(1, 1, 0);                // layer 2: M=m1 -> acc1
    k_layer3pre<<<NB_V, 256>>>(b2);
    k_scatter<<<NB_E2, 256>>>(0, 0, 0);                // layer 3: M=m0 -> acc0 (F=8)
    k_out<<<NB_V, 256>>>(W3, b3, fcw, fcb, out);
}